// round 3
// baseline (speedup 1.0000x reference)
#include <cuda_runtime.h>
#include <cstdint>

// Problem constants (fixed by the dataset)
#define DD    128          // feature dim
#define NMAX  20000        // nodes
#define NH    8            // heads
#define HDIM  16           // head dim

// ---------------- device scratch (no allocations allowed) ----------------
__device__ float g_P [NMAX * DD];   // node projection  P = x@Wp^T + bp
__device__ float g_S [NMAX * DD];   // aggregated attention outputs per node
__device__ float g_Ht[NMAX * DD];   // hidden layer
__device__ float g_deg[NMAX];       // in-degree (float)
__device__ float g_Wc[DD * DD];     // W1b @ Wm  (folded)
__device__ float g_bc[DD];          // W1b @ bm
__device__ int   g_e64;             // 1 if edges are int64, 0 if int32

// ---------------- edge dtype detection ----------------
__global__ void k_detect(const long long* __restrict__ e64, int elems, int N) {
    if (threadIdx.x == 0 && blockIdx.x == 0) {
        int cnt = elems < 256 ? elems : 256;
        int ok = 1;
        for (int i = 0; i < cnt; i++) {
            long long v = e64[i];
            if (v < 0 || v >= (long long)N) { ok = 0; break; }
        }
        g_e64 = ok;
    }
}

// ---------------- fold Wm into W1's second half ----------------
// Wc[j][k] = sum_i W1[j][128+i] * Wm[i][k];  bc[j] = sum_i W1[j][128+i]*bm[i]
__global__ __launch_bounds__(DD) void k_fold(const float* __restrict__ W1,
                                             const float* __restrict__ Wm,
                                             const float* __restrict__ bm) {
    __shared__ float w1b[DD];
    int j = blockIdx.x, k = threadIdx.x;
    w1b[k] = W1[j * (2 * DD) + DD + k];
    __syncthreads();
    float acc = 0.f;
#pragma unroll 8
    for (int i = 0; i < DD; i++) acc = fmaf(w1b[i], Wm[i * DD + k], acc);
    g_Wc[j * DD + k] = acc;
    if (k == 0) {
        float b = 0.f;
        for (int i = 0; i < DD; i++) b = fmaf(w1b[i], bm[i], b);
        g_bc[j] = b;
    }
}

// ---------------- shared fp32 GEMM tile: 64 rows x 128 cols, k=128 ----------------
// C[r][c] += sum_k A[r][k] * B[c][k]   (B row stride ldb)
struct SmemGemm {
    float sAT[32][68];    // sAT[kk][r]  (pad 68: conflict-free f4 broadcast)
    float sBT[32][132];   // sBT[kk][j]  (pad 132: 16B-aligned rows)
};

__device__ __forceinline__ void gemm64x128(const float* __restrict__ A,
                                           const float* __restrict__ B, int ldb,
                                           int rbase, int nrows, int tid,
                                           float acc[4][8], SmemGemm* sm) {
    const int tx = tid & 15, ty = tid >> 4;
    for (int kb = 0; kb < DD; kb += 32) {
        // stage B chunk transposed: sBT[kk][j] = B[j][kb+kk]
#pragma unroll
        for (int it = 0; it < 4; it++) {
            int i = tid + it * 256;            // 0..1023
            int j = i >> 3, f4 = i & 7;
            float4 v = *(const float4*)&B[j * ldb + kb + f4 * 4];
            sm->sBT[f4 * 4 + 0][j] = v.x;
            sm->sBT[f4 * 4 + 1][j] = v.y;
            sm->sBT[f4 * 4 + 2][j] = v.z;
            sm->sBT[f4 * 4 + 3][j] = v.w;
        }
        // stage A chunk transposed: sAT[kk][r] = A[rbase+r][kb+kk]
#pragma unroll
        for (int it = 0; it < 2; it++) {
            int i = tid + it * 256;            // 0..511
            int r = i >> 3, f4 = i & 7;
            int row = rbase + r;
            if (row >= nrows) row = nrows - 1; // clamp (stores guarded later)
            float4 v = *(const float4*)&A[row * DD + kb + f4 * 4];
            sm->sAT[f4 * 4 + 0][r] = v.x;
            sm->sAT[f4 * 4 + 1][r] = v.y;
            sm->sAT[f4 * 4 + 2][r] = v.z;
            sm->sAT[f4 * 4 + 3][r] = v.w;
        }
        __syncthreads();
#pragma unroll 8
        for (int k = 0; k < 32; k++) {
            float4 a  = *(const float4*)&sm->sAT[k][ty * 4];
            float4 b0 = *(const float4*)&sm->sBT[k][tx * 4];
            float4 b1 = *(const float4*)&sm->sBT[k][64 + tx * 4];
            float av[4] = {a.x, a.y, a.z, a.w};
            float bv[8] = {b0.x, b0.y, b0.z, b0.w, b1.x, b1.y, b1.z, b1.w};
#pragma unroll
            for (int i = 0; i < 4; i++)
#pragma unroll
                for (int jj = 0; jj < 8; jj++)
                    acc[i][jj] = fmaf(av[i], bv[jj], acc[i][jj]);
        }
        __syncthreads();
    }
}

// ---------------- kernel A: P = x@Wp^T + bp; also zero S and deg ----------------
__global__ __launch_bounds__(256) void k_proj(const float* __restrict__ x,
                                              const float* __restrict__ Wp,
                                              const float* __restrict__ bp, int N) {
    __shared__ SmemGemm sm;
    float acc[4][8] = {};
    const int tid = threadIdx.x;
    const int rbase = blockIdx.x * 64;
    gemm64x128(x, Wp, DD, rbase, N, tid, acc, &sm);
    const int tx = tid & 15, ty = tid >> 4;
#pragma unroll
    for (int i = 0; i < 4; i++) {
        int row = rbase + ty * 4 + i;
        if (row < N) {
#pragma unroll
            for (int half = 0; half < 2; half++) {
                int c = half * 64 + tx * 4;
                float4 v;
                v.x = acc[i][half * 4 + 0] + bp[c + 0];
                v.y = acc[i][half * 4 + 1] + bp[c + 1];
                v.z = acc[i][half * 4 + 2] + bp[c + 2];
                v.w = acc[i][half * 4 + 3] + bp[c + 3];
                *(float4*)&g_P[row * DD + c] = v;
            }
        }
    }
    // zero accumulation buffers for this block's rows
    for (int i = tid; i < 64 * DD; i += 256) {
        int row = rbase + (i >> 7);
        if (row < N) g_S[row * DD + (i & 127)] = 0.f;
    }
    for (int i = tid; i < 64; i += 256)
        if (rbase + i < N) g_deg[rbase + i] = 0.f;
}

// ---------------- kernel B: per-edge attention, scatter-add into g_S ----------------
// 16 threads per edge (thread = score row n); 2 edges per warp; 16 edges per block.
__global__ __launch_bounds__(256) void k_edge(const void* __restrict__ edges_raw,
                                              int E) {
    __shared__ float buf[8][4][136];  // per warp: q0,k0,q1,k1 (rows padded -> disjoint banks)
    __shared__ float ob[8][2][136];   // per warp: staged outputs for the 2 edges

    const int tid  = threadIdx.x;
    const int w    = tid >> 5;
    const int lane = tid & 31;
    const int g    = lane >> 4;       // which edge in the warp pair
    const int n    = lane & 15;       // score row / HD index
    const int e0   = blockIdx.x * 16 + w * 2;
    const int use64 = g_e64;

    // cooperative load of 4 P-rows (q0,k0,q1,k1): lane role rr = lane>>3
    const int rr = lane >> 3;         // 0:q(e0) 1:k(e0) 2:q(e1) 3:k(e1)
    const int li = lane & 7;
    const int loadE = e0 + (rr >> 1);
    if (loadE < E) {
        int node;
        if (use64) {
            const long long* E64 = (const long long*)edges_raw;
            node = (int)E64[loadE * 2 + (rr & 1)];
        } else {
            const int* E32 = (const int*)edges_raw;
            node = E32[loadE * 2 + (rr & 1)];
        }
        const float4* P4 = (const float4*)g_P;
#pragma unroll
        for (int jj = 0; jj < 4; jj++) {
            float4 v = P4[node * 32 + li + jj * 8];
            *(float4*)&buf[w][rr][(li + jj * 8) * 4] = v;
        }
    }
    __syncwarp();

    const int myE = e0 + g;
    const bool active = (myE < E);
    int c = 0;
    if (active) {
        if (use64) {
            const long long* E64 = (const long long*)edges_raw;
            c = (int)E64[myE * 2 + 1];
        } else {
            const int* E32 = (const int*)edges_raw;
            c = E32[myE * 2 + 1];
        }
        const float* qr = buf[w][g * 2];
        const float* kr = buf[w][g * 2 + 1];

        float q[NH];
#pragma unroll
        for (int h = 0; h < NH; h++) q[h] = qr[h * HDIM + n];

        // scores: s[n][m] = (1/sqrt(8)) * sum_h q[h][n]*k[h][m]
        float s[HDIM];
#pragma unroll
        for (int m = 0; m < HDIM; m++) {
            float a = 0.f;
#pragma unroll
            for (int h = 0; h < NH; h++) a = fmaf(q[h], kr[h * HDIM + m], a);
            s[m] = a * 0.3535533906f;
        }
        // row-local softmax (no cross-thread comms needed)
        float mx = s[0];
#pragma unroll
        for (int m = 1; m < HDIM; m++) mx = fmaxf(mx, s[m]);
        float sum = 0.f;
#pragma unroll
        for (int m = 0; m < HDIM; m++) {
            float p = __expf(s[m] - mx);
            s[m] = p;
            sum += p;
        }
        float inv = 1.0f / sum;
        // out[h][n] = sum_m prob[n][m] * v[h][m]  (v == k)
#pragma unroll
        for (int h = 0; h < NH; h++) {
            float o = 0.f;
#pragma unroll
            for (int m = 0; m < HDIM; m++) o = fmaf(s[m], kr[h * HDIM + m], o);
            ob[w][g][h * HDIM + n] = o * inv;
        }
        if (n == 0) atomicAdd(&g_deg[c], 1.0f);
    }
    __syncwarp();
    // transpose-staged vector reduction: each thread owns 8 contiguous floats
    if (active) {
        float4 v0 = *(float4*)&ob[w][g][n * 8];
        float4 v1 = *(float4*)&ob[w][g][n * 8 + 4];
        float* dst = &g_S[c * DD + n * 8];
        asm volatile("red.global.add.v4.f32 [%0], {%1,%2,%3,%4};"
                     :: "l"(dst), "f"(v0.x), "f"(v0.y), "f"(v0.z), "f"(v0.w)
                     : "memory");
        asm volatile("red.global.add.v4.f32 [%0], {%1,%2,%3,%4};"
                     :: "l"(dst + 4), "f"(v1.x), "f"(v1.y), "f"(v1.z), "f"(v1.w)
                     : "memory");
    }
}

// ---------------- kernel C2: h = relu(x@W1a^T + S@Wc^T + deg*bc + b1) ----------------
__global__ __launch_bounds__(256) void k_mlp1(const float* __restrict__ x,
                                              const float* __restrict__ W1,
                                              const float* __restrict__ b1, int N) {
    __shared__ SmemGemm sm;
    float acc[4][8] = {};
    const int tid = threadIdx.x;
    const int rbase = blockIdx.x * 64;
    gemm64x128(x, W1, 2 * DD, rbase, N, tid, acc, &sm);   // x @ W1a^T (W1 row stride 256)
    gemm64x128(g_S, g_Wc, DD, rbase, N, tid, acc, &sm);   // S @ Wc^T
    const int tx = tid & 15, ty = tid >> 4;
#pragma unroll
    for (int i = 0; i < 4; i++) {
        int row = rbase + ty * 4 + i;
        if (row < N) {
            float dv = g_deg[row];
#pragma unroll
            for (int half = 0; half < 2; half++) {
                int c = half * 64 + tx * 4;
                float4 v;
                v.x = fmaxf(acc[i][half * 4 + 0] + b1[c + 0] + dv * g_bc[c + 0], 0.f);
                v.y = fmaxf(acc[i][half * 4 + 1] + b1[c + 1] + dv * g_bc[c + 1], 0.f);
                v.z = fmaxf(acc[i][half * 4 + 2] + b1[c + 2] + dv * g_bc[c + 2], 0.f);
                v.w = fmaxf(acc[i][half * 4 + 3] + b1[c + 3] + dv * g_bc[c + 3], 0.f);
                *(float4*)&g_Ht[row * DD + c] = v;
            }
        }
    }
}

// ---------------- kernel C3: y = h@W2^T + b2 ----------------
__global__ __launch_bounds__(256) void k_out(const float* __restrict__ W2,
                                             const float* __restrict__ b2,
                                             float* __restrict__ out, int N) {
    __shared__ SmemGemm sm;
    float acc[4][8] = {};
    const int tid = threadIdx.x;
    const int rbase = blockIdx.x * 64;
    gemm64x128(g_Ht, W2, DD, rbase, N, tid, acc, &sm);
    const int tx = tid & 15, ty = tid >> 4;
#pragma unroll
    for (int i = 0; i < 4; i++) {
        int row = rbase + ty * 4 + i;
        if (row < N) {
#pragma unroll
            for (int half = 0; half < 2; half++) {
                int c = half * 64 + tx * 4;
                float4 v;
                v.x = acc[i][half * 4 + 0] + b2[c + 0];
                v.y = acc[i][half * 4 + 1] + b2[c + 1];
                v.z = acc[i][half * 4 + 2] + b2[c + 2];
                v.w = acc[i][half * 4 + 3] + b2[c + 3];
                *(float4*)&out[row * DD + c] = v;
            }
        }
    }
}

// ---------------- launch ----------------
extern "C" void kernel_launch(void* const* d_in, const int* in_sizes, int n_in,
                              void* d_out, int out_size) {
    const float* x     = (const float*)d_in[0];
    const void*  edges = d_in[1];
    const float* Wp    = (const float*)d_in[2];
    const float* bp    = (const float*)d_in[3];
    // Wm = d_in[4], bm = d_in[5] used only in fold
    const float* Wm    = (const float*)d_in[4];
    const float* bm    = (const float*)d_in[5];
    const float* W1    = (const float*)d_in[6];
    const float* b1    = (const float*)d_in[7];
    const float* W2    = (const float*)d_in[8];
    const float* b2    = (const float*)d_in[9];
    float* out = (float*)d_out;

    const int N = in_sizes[0] / DD;   // 20000
    const int E = in_sizes[1] / 2;    // 320000
    const int gN = (N + 63) / 64;

    k_detect<<<1, 32>>>((const long long*)edges, E * 2, N);
    k_fold<<<DD, DD>>>(W1, Wm, bm);
    k_proj<<<gN, 256>>>(x, Wp, bp, N);
    k_edge<<<(E + 15) / 16, 256>>>(edges, E);
    k_mlp1<<<gN, 256>>>(x, W1, b1, N);
    k_out<<<gN, 256>>>(W2, b2, out, N);
}

// round 4
// speedup vs baseline: 1.0854x; 1.0854x over previous
#include <cuda_runtime.h>
#include <cstdint>

// Problem constants (fixed by the dataset)
#define DD    128          // feature dim
#define NMAX  20000        // nodes
#define NH    8            // heads
#define HDIM  16           // head dim

// ---------------- device scratch (no allocations allowed) ----------------
__device__ float g_P [NMAX * DD];   // node projection  P = x@Wp^T + bp
__device__ float g_S [NMAX * DD];   // aggregated attention outputs per node
__device__ float g_Ht[NMAX * DD];   // hidden layer
__device__ float g_deg[NMAX];       // in-degree (float)
__device__ float g_Wc[DD * DD];     // W1b @ Wm  (folded)
__device__ float g_bc[DD];          // W1b @ bm
__device__ int   g_e64;             // 1 if edges are int64, 0 if int32

// ---------------- edge dtype detection ----------------
__global__ void k_detect(const long long* __restrict__ e64, int elems, int N) {
    if (threadIdx.x == 0 && blockIdx.x == 0) {
        int cnt = elems < 256 ? elems : 256;
        int ok = 1;
        for (int i = 0; i < cnt; i++) {
            long long v = e64[i];
            if (v < 0 || v >= (long long)N) { ok = 0; break; }
        }
        g_e64 = ok;
    }
}

// ---------------- fold Wm into W1's second half ----------------
// Wc[j][k] = sum_i W1[j][128+i] * Wm[i][k];  bc[j] = sum_i W1[j][128+i]*bm[i]
__global__ __launch_bounds__(DD) void k_fold(const float* __restrict__ W1,
                                             const float* __restrict__ Wm,
                                             const float* __restrict__ bm) {
    __shared__ float w1b[DD];
    int j = blockIdx.x, k = threadIdx.x;
    w1b[k] = W1[j * (2 * DD) + DD + k];
    __syncthreads();
    float acc = 0.f;
#pragma unroll 8
    for (int i = 0; i < DD; i++) acc = fmaf(w1b[i], Wm[i * DD + k], acc);
    g_Wc[j * DD + k] = acc;
    if (k == 0) {
        float b = 0.f;
        for (int i = 0; i < DD; i++) b = fmaf(w1b[i], bm[i], b);
        g_bc[j] = b;
    }
}

// ---------------- shared fp32 GEMM tile: 64 rows x 128 cols, k=128 ----------------
// C[r][c] += sum_k A[r][k] * B[c][k]   (B row stride ldb)
struct SmemGemm {
    float sAT[32][68];    // sAT[kk][r]  (pad 68: conflict-free f4 broadcast)
    float sBT[32][132];   // sBT[kk][j]  (pad 132: 16B-aligned rows)
};

__device__ __forceinline__ void gemm64x128(const float* __restrict__ A,
                                           const float* __restrict__ B, int ldb,
                                           int rbase, int nrows, int tid,
                                           float acc[4][8], SmemGemm* sm) {
    const int tx = tid & 15, ty = tid >> 4;
    for (int kb = 0; kb < DD; kb += 32) {
        // stage B chunk transposed: sBT[kk][j] = B[j][kb+kk]
#pragma unroll
        for (int it = 0; it < 4; it++) {
            int i = tid + it * 256;            // 0..1023
            int j = i >> 3, f4 = i & 7;
            float4 v = *(const float4*)&B[j * ldb + kb + f4 * 4];
            sm->sBT[f4 * 4 + 0][j] = v.x;
            sm->sBT[f4 * 4 + 1][j] = v.y;
            sm->sBT[f4 * 4 + 2][j] = v.z;
            sm->sBT[f4 * 4 + 3][j] = v.w;
        }
        // stage A chunk transposed: sAT[kk][r] = A[rbase+r][kb+kk]
#pragma unroll
        for (int it = 0; it < 2; it++) {
            int i = tid + it * 256;            // 0..511
            int r = i >> 3, f4 = i & 7;
            int row = rbase + r;
            if (row >= nrows) row = nrows - 1; // clamp (stores guarded later)
            float4 v = *(const float4*)&A[row * DD + kb + f4 * 4];
            sm->sAT[f4 * 4 + 0][r] = v.x;
            sm->sAT[f4 * 4 + 1][r] = v.y;
            sm->sAT[f4 * 4 + 2][r] = v.z;
            sm->sAT[f4 * 4 + 3][r] = v.w;
        }
        __syncthreads();
#pragma unroll 8
        for (int k = 0; k < 32; k++) {
            float4 a  = *(const float4*)&sm->sAT[k][ty * 4];
            float4 b0 = *(const float4*)&sm->sBT[k][tx * 4];
            float4 b1 = *(const float4*)&sm->sBT[k][64 + tx * 4];
            float av[4] = {a.x, a.y, a.z, a.w};
            float bv[8] = {b0.x, b0.y, b0.z, b0.w, b1.x, b1.y, b1.z, b1.w};
#pragma unroll
            for (int i = 0; i < 4; i++)
#pragma unroll
                for (int jj = 0; jj < 8; jj++)
                    acc[i][jj] = fmaf(av[i], bv[jj], acc[i][jj]);
        }
        __syncthreads();
    }
}

// ---------------- kernel A: P = x@Wp^T + bp; also zero S and deg ----------------
__global__ __launch_bounds__(256) void k_proj(const float* __restrict__ x,
                                              const float* __restrict__ Wp,
                                              const float* __restrict__ bp, int N) {
    __shared__ SmemGemm sm;
    float acc[4][8] = {};
    const int tid = threadIdx.x;
    const int rbase = blockIdx.x * 64;
    gemm64x128(x, Wp, DD, rbase, N, tid, acc, &sm);
    const int tx = tid & 15, ty = tid >> 4;
#pragma unroll
    for (int i = 0; i < 4; i++) {
        int row = rbase + ty * 4 + i;
        if (row < N) {
#pragma unroll
            for (int half = 0; half < 2; half++) {
                int c = half * 64 + tx * 4;
                float4 v;
                v.x = acc[i][half * 4 + 0] + bp[c + 0];
                v.y = acc[i][half * 4 + 1] + bp[c + 1];
                v.z = acc[i][half * 4 + 2] + bp[c + 2];
                v.w = acc[i][half * 4 + 3] + bp[c + 3];
                *(float4*)&g_P[row * DD + c] = v;
            }
        }
    }
    // zero accumulation buffers for this block's rows
    for (int i = tid; i < 64 * DD; i += 256) {
        int row = rbase + (i >> 7);
        if (row < N) g_S[row * DD + (i & 127)] = 0.f;
    }
    for (int i = tid; i < 64; i += 256)
        if (rbase + i < N) g_deg[rbase + i] = 0.f;
}

// ---------------- kernel B: per-edge attention, scatter-add into g_S ----------------
// 16 threads per edge (thread = score row n); 2 edges per warp; 16 edges per block.
// v2: float4 LDS for k rows (4x fewer LDS issues), launch_bounds(256,2) to get
// 2 blocks/SM (occupancy 12% -> 25%).
__global__ __launch_bounds__(256, 2) void k_edge(const void* __restrict__ edges_raw,
                                                 int E) {
    __shared__ float buf[8][4][136];  // per warp: q0,k0,q1,k1 (rows padded; 16B-aligned)
    __shared__ float ob[8][2][136];   // per warp: staged outputs for the 2 edges

    const int tid  = threadIdx.x;
    const int w    = tid >> 5;
    const int lane = tid & 31;
    const int g    = lane >> 4;       // which edge in the warp pair
    const int n    = lane & 15;       // score row / HD index
    const int e0   = blockIdx.x * 16 + w * 2;
    const int use64 = g_e64;

    // cooperative load of 4 P-rows (q0,k0,q1,k1): lane role rr = lane>>3
    const int rr = lane >> 3;         // 0:q(e0) 1:k(e0) 2:q(e1) 3:k(e1)
    const int li = lane & 7;
    const int loadE = e0 + (rr >> 1);
    if (loadE < E) {
        int node;
        if (use64) {
            const long long* E64 = (const long long*)edges_raw;
            node = (int)E64[loadE * 2 + (rr & 1)];
        } else {
            const int* E32 = (const int*)edges_raw;
            node = E32[loadE * 2 + (rr & 1)];
        }
        const float4* P4 = (const float4*)g_P;
#pragma unroll
        for (int jj = 0; jj < 4; jj++) {
            float4 v = P4[node * 32 + li + jj * 8];
            *(float4*)&buf[w][rr][(li + jj * 8) * 4] = v;
        }
    }
    __syncwarp();

    const int myE = e0 + g;
    const bool active = (myE < E);
    int c = 0;
    if (active) {
        if (use64) {
            const long long* E64 = (const long long*)edges_raw;
            c = (int)E64[myE * 2 + 1];
        } else {
            const int* E32 = (const int*)edges_raw;
            c = E32[myE * 2 + 1];
        }
        const float*  qr  = buf[w][g * 2];
        const float4* kr4 = (const float4*)buf[w][g * 2 + 1];   // 16B aligned (544B rows)

        float q[NH];
#pragma unroll
        for (int h = 0; h < NH; h++) q[h] = qr[h * HDIM + n];

        // scores: s[n][m] = (1/sqrt(8)) * sum_h q[h][n]*k[h][m]
        // k row h is contiguous: read as 4x float4 -> 4 FMAs each (broadcast LDS.128)
        float s[HDIM] = {};
#pragma unroll
        for (int h = 0; h < NH; h++) {
            float4 k0 = kr4[h * 4 + 0];
            float4 k1 = kr4[h * 4 + 1];
            float4 k2 = kr4[h * 4 + 2];
            float4 k3 = kr4[h * 4 + 3];
            float qh = q[h];
            s[0]  = fmaf(qh, k0.x, s[0]);   s[1]  = fmaf(qh, k0.y, s[1]);
            s[2]  = fmaf(qh, k0.z, s[2]);   s[3]  = fmaf(qh, k0.w, s[3]);
            s[4]  = fmaf(qh, k1.x, s[4]);   s[5]  = fmaf(qh, k1.y, s[5]);
            s[6]  = fmaf(qh, k1.z, s[6]);   s[7]  = fmaf(qh, k1.w, s[7]);
            s[8]  = fmaf(qh, k2.x, s[8]);   s[9]  = fmaf(qh, k2.y, s[9]);
            s[10] = fmaf(qh, k2.z, s[10]);  s[11] = fmaf(qh, k2.w, s[11]);
            s[12] = fmaf(qh, k3.x, s[12]);  s[13] = fmaf(qh, k3.y, s[13]);
            s[14] = fmaf(qh, k3.z, s[14]);  s[15] = fmaf(qh, k3.w, s[15]);
        }
        // row-local softmax (thread-local; pairwise max tree for short dep chain)
        float mx01 = fmaxf(s[0], s[1]);
#pragma unroll
        for (int m = 2; m < HDIM; m += 2) mx01 = fmaxf(mx01, fmaxf(s[m], s[m + 1]));
        const float mx = mx01;
        float sum = 0.f;
#pragma unroll
        for (int m = 0; m < HDIM; m++) {
            float p = __expf(fmaf(s[m], 0.3535533906f, -mx * 0.3535533906f));
            s[m] = p;
            sum += p;
        }
        const float inv = 1.0f / sum;
        // out[h][n] = inv * sum_m prob[n][m] * k[h][m]   (v == k)
#pragma unroll
        for (int h = 0; h < NH; h++) {
            float4 k0 = kr4[h * 4 + 0];
            float4 k1 = kr4[h * 4 + 1];
            float4 k2 = kr4[h * 4 + 2];
            float4 k3 = kr4[h * 4 + 3];
            float o = s[0] * k0.x;
            o = fmaf(s[1],  k0.y, o);  o = fmaf(s[2],  k0.z, o);  o = fmaf(s[3],  k0.w, o);
            o = fmaf(s[4],  k1.x, o);  o = fmaf(s[5],  k1.y, o);  o = fmaf(s[6],  k1.z, o);
            o = fmaf(s[7],  k1.w, o);  o = fmaf(s[8],  k2.x, o);  o = fmaf(s[9],  k2.y, o);
            o = fmaf(s[10], k2.z, o);  o = fmaf(s[11], k2.w, o);  o = fmaf(s[12], k3.x, o);
            o = fmaf(s[13], k3.y, o);  o = fmaf(s[14], k3.z, o);  o = fmaf(s[15], k3.w, o);
            ob[w][g][h * HDIM + n] = o * inv;
        }
        if (n == 0) atomicAdd(&g_deg[c], 1.0f);
    }
    __syncwarp();
    // transpose-staged vector reduction: each thread owns 8 contiguous floats
    if (active) {
        float4 v0 = *(float4*)&ob[w][g][n * 8];
        float4 v1 = *(float4*)&ob[w][g][n * 8 + 4];
        float* dst = &g_S[c * DD + n * 8];
        asm volatile("red.global.add.v4.f32 [%0], {%1,%2,%3,%4};"
                     :: "l"(dst), "f"(v0.x), "f"(v0.y), "f"(v0.z), "f"(v0.w)
                     : "memory");
        asm volatile("red.global.add.v4.f32 [%0], {%1,%2,%3,%4};"
                     :: "l"(dst + 4), "f"(v1.x), "f"(v1.y), "f"(v1.z), "f"(v1.w)
                     : "memory");
    }
}

// ---------------- kernel C2: h = relu(x@W1a^T + S@Wc^T + deg*bc + b1) ----------------
__global__ __launch_bounds__(256) void k_mlp1(const float* __restrict__ x,
                                              const float* __restrict__ W1,
                                              const float* __restrict__ b1, int N) {
    __shared__ SmemGemm sm;
    float acc[4][8] = {};
    const int tid = threadIdx.x;
    const int rbase = blockIdx.x * 64;
    gemm64x128(x, W1, 2 * DD, rbase, N, tid, acc, &sm);   // x @ W1a^T (W1 row stride 256)
    gemm64x128(g_S, g_Wc, DD, rbase, N, tid, acc, &sm);   // S @ Wc^T
    const int tx = tid & 15, ty = tid >> 4;
#pragma unroll
    for (int i = 0; i < 4; i++) {
        int row = rbase + ty * 4 + i;
        if (row < N) {
            float dv = g_deg[row];
#pragma unroll
            for (int half = 0; half < 2; half++) {
                int c = half * 64 + tx * 4;
                float4 v;
                v.x = fmaxf(acc[i][half * 4 + 0] + b1[c + 0] + dv * g_bc[c + 0], 0.f);
                v.y = fmaxf(acc[i][half * 4 + 1] + b1[c + 1] + dv * g_bc[c + 1], 0.f);
                v.z = fmaxf(acc[i][half * 4 + 2] + b1[c + 2] + dv * g_bc[c + 2], 0.f);
                v.w = fmaxf(acc[i][half * 4 + 3] + b1[c + 3] + dv * g_bc[c + 3], 0.f);
                *(float4*)&g_Ht[row * DD + c] = v;
            }
        }
    }
}

// ---------------- kernel C3: y = h@W2^T + b2 ----------------
__global__ __launch_bounds__(256) void k_out(const float* __restrict__ W2,
                                             const float* __restrict__ b2,
                                             float* __restrict__ out, int N) {
    __shared__ SmemGemm sm;
    float acc[4][8] = {};
    const int tid = threadIdx.x;
    const int rbase = blockIdx.x * 64;
    gemm64x128(g_Ht, W2, DD, rbase, N, tid, acc, &sm);
    const int tx = tid & 15, ty = tid >> 4;
#pragma unroll
    for (int i = 0; i < 4; i++) {
        int row = rbase + ty * 4 + i;
        if (row < N) {
#pragma unroll
            for (int half = 0; half < 2; half++) {
                int c = half * 64 + tx * 4;
                float4 v;
                v.x = acc[i][half * 4 + 0] + b2[c + 0];
                v.y = acc[i][half * 4 + 1] + b2[c + 1];
                v.z = acc[i][half * 4 + 2] + b2[c + 2];
                v.w = acc[i][half * 4 + 3] + b2[c + 3];
                *(float4*)&out[row * DD + c] = v;
            }
        }
    }
}

// ---------------- launch ----------------
extern "C" void kernel_launch(void* const* d_in, const int* in_sizes, int n_in,
                              void* d_out, int out_size) {
    const float* x     = (const float*)d_in[0];
    const void*  edges = d_in[1];
    const float* Wp    = (const float*)d_in[2];
    const float* bp    = (const float*)d_in[3];
    const float* Wm    = (const float*)d_in[4];
    const float* bm    = (const float*)d_in[5];
    const float* W1    = (const float*)d_in[6];
    const float* b1    = (const float*)d_in[7];
    const float* W2    = (const float*)d_in[8];
    const float* b2    = (const float*)d_in[9];
    float* out = (float*)d_out;

    const int N = in_sizes[0] / DD;   // 20000
    const int E = in_sizes[1] / 2;    // 320000
    const int gN = (N + 63) / 64;

    k_detect<<<1, 32>>>((const long long*)edges, E * 2, N);
    k_fold<<<DD, DD>>>(W1, Wm, bm);
    k_proj<<<gN, 256>>>(x, Wp, bp, N);
    k_edge<<<(E + 15) / 16, 256>>>(edges, E);
    k_mlp1<<<gN, 256>>>(x, W1, b1, N);
    k_out<<<gN, 256>>>(W2, b2, out, N);
}

// round 5
// speedup vs baseline: 1.5398x; 1.4187x over previous
#include <cuda_runtime.h>
#include <cstdint>

// Problem constants (fixed by the dataset)
#define DD    128          // feature dim
#define NMAX  20000        // nodes
#define NH    8            // heads
#define HDIM  16           // head dim

// ---------------- device scratch (no allocations allowed) ----------------
__device__ float g_P [NMAX * DD];   // node projection  P = x@Wp^T + bp
__device__ float g_S [NMAX * DD];   // aggregated attention outputs per node
__device__ float g_Ht[NMAX * DD];   // hidden layer
__device__ float g_deg[NMAX];       // in-degree (float)
__device__ float g_Wc[DD * DD];     // W1b @ Wm  (folded)
__device__ float g_bc[DD];          // W1b @ bm
__device__ int   g_e64;             // 1 if edges are int64, 0 if int32

// ---------------- edge dtype detection ----------------
__global__ void k_detect(const long long* __restrict__ e64, int elems, int N) {
    if (threadIdx.x == 0 && blockIdx.x == 0) {
        int cnt = elems < 256 ? elems : 256;
        int ok = 1;
        for (int i = 0; i < cnt; i++) {
            long long v = e64[i];
            if (v < 0 || v >= (long long)N) { ok = 0; break; }
        }
        g_e64 = ok;
    }
}

// ---------------- fold Wm into W1's second half ----------------
// Wc[j][k] = sum_i W1[j][128+i] * Wm[i][k];  bc[j] = sum_i W1[j][128+i]*bm[i]
__global__ __launch_bounds__(DD) void k_fold(const float* __restrict__ W1,
                                             const float* __restrict__ Wm,
                                             const float* __restrict__ bm) {
    __shared__ float w1b[DD];
    int j = blockIdx.x, k = threadIdx.x;
    w1b[k] = W1[j * (2 * DD) + DD + k];
    __syncthreads();
    float acc = 0.f;
#pragma unroll 8
    for (int i = 0; i < DD; i++) acc = fmaf(w1b[i], Wm[i * DD + k], acc);
    g_Wc[j * DD + k] = acc;
    if (k == 0) {
        float b = 0.f;
        for (int i = 0; i < DD; i++) b = fmaf(w1b[i], bm[i], b);
        g_bc[j] = b;
    }
}

// ---------------- shared fp32 GEMM tile: 64 rows x 128 cols, k=128 ----------------
// C[r][c] += sum_k A[r][k] * B[c][k]   (B row stride ldb)
struct SmemGemm {
    float sAT[32][68];    // sAT[kk][r]  (pad 68: conflict-free f4 broadcast)
    float sBT[32][132];   // sBT[kk][j]  (pad 132: 16B-aligned rows)
};

__device__ __forceinline__ void gemm64x128(const float* __restrict__ A,
                                           const float* __restrict__ B, int ldb,
                                           int rbase, int nrows, int tid,
                                           float acc[4][8], SmemGemm* sm) {
    const int tx = tid & 15, ty = tid >> 4;
    for (int kb = 0; kb < DD; kb += 32) {
        // stage B chunk transposed: sBT[kk][j] = B[j][kb+kk]
#pragma unroll
        for (int it = 0; it < 4; it++) {
            int i = tid + it * 256;            // 0..1023
            int j = i >> 3, f4 = i & 7;
            float4 v = *(const float4*)&B[j * ldb + kb + f4 * 4];
            sm->sBT[f4 * 4 + 0][j] = v.x;
            sm->sBT[f4 * 4 + 1][j] = v.y;
            sm->sBT[f4 * 4 + 2][j] = v.z;
            sm->sBT[f4 * 4 + 3][j] = v.w;
        }
        // stage A chunk transposed: sAT[kk][r] = A[rbase+r][kb+kk]
#pragma unroll
        for (int it = 0; it < 2; it++) {
            int i = tid + it * 256;            // 0..511
            int r = i >> 3, f4 = i & 7;
            int row = rbase + r;
            if (row >= nrows) row = nrows - 1; // clamp (stores guarded later)
            float4 v = *(const float4*)&A[row * DD + kb + f4 * 4];
            sm->sAT[f4 * 4 + 0][r] = v.x;
            sm->sAT[f4 * 4 + 1][r] = v.y;
            sm->sAT[f4 * 4 + 2][r] = v.z;
            sm->sAT[f4 * 4 + 3][r] = v.w;
        }
        __syncthreads();
#pragma unroll 8
        for (int k = 0; k < 32; k++) {
            float4 a  = *(const float4*)&sm->sAT[k][ty * 4];
            float4 b0 = *(const float4*)&sm->sBT[k][tx * 4];
            float4 b1 = *(const float4*)&sm->sBT[k][64 + tx * 4];
            float av[4] = {a.x, a.y, a.z, a.w};
            float bv[8] = {b0.x, b0.y, b0.z, b0.w, b1.x, b1.y, b1.z, b1.w};
#pragma unroll
            for (int i = 0; i < 4; i++)
#pragma unroll
                for (int jj = 0; jj < 8; jj++)
                    acc[i][jj] = fmaf(av[i], bv[jj], acc[i][jj]);
        }
        __syncthreads();
    }
}

// ---------------- kernel A: P = x@Wp^T + bp; also zero S and deg ----------------
__global__ __launch_bounds__(256) void k_proj(const float* __restrict__ x,
                                              const float* __restrict__ Wp,
                                              const float* __restrict__ bp, int N) {
    __shared__ SmemGemm sm;
    float acc[4][8] = {};
    const int tid = threadIdx.x;
    const int rbase = blockIdx.x * 64;
    gemm64x128(x, Wp, DD, rbase, N, tid, acc, &sm);
    const int tx = tid & 15, ty = tid >> 4;
#pragma unroll
    for (int i = 0; i < 4; i++) {
        int row = rbase + ty * 4 + i;
        if (row < N) {
#pragma unroll
            for (int half = 0; half < 2; half++) {
                int c = half * 64 + tx * 4;
                float4 v;
                v.x = acc[i][half * 4 + 0] + bp[c + 0];
                v.y = acc[i][half * 4 + 1] + bp[c + 1];
                v.z = acc[i][half * 4 + 2] + bp[c + 2];
                v.w = acc[i][half * 4 + 3] + bp[c + 3];
                *(float4*)&g_P[row * DD + c] = v;
            }
        }
    }
    // zero accumulation buffers for this block's rows
    for (int i = tid; i < 64 * DD; i += 256) {
        int row = rbase + (i >> 7);
        if (row < N) g_S[row * DD + (i & 127)] = 0.f;
    }
    for (int i = tid; i < 64; i += 256)
        if (rbase + i < N) g_deg[rbase + i] = 0.f;
}

// ---------------- kernel B: per-edge attention, scatter-add into g_S ----------------
// v3: 4 threads per edge. Thread t owns score rows n = 4t..4t+3. The 16x16
// score block + softmax are fully register-resident (no cross-thread comms,
// no shared memory). q/k rows are read straight from g_P (L2-resident, k-row
// reuse hits L1). Output epilogue: out[h][4t..4t+3] is a contiguous float4 at
// feature offset h*16+4t -> direct red.global.add.v4 per head, zero staging.
__global__ __launch_bounds__(128, 4) void k_edge(const void* __restrict__ edges_raw,
                                                 int E) {
    const int gt = blockIdx.x * 128 + threadIdx.x;
    const int e  = gt >> 2;            // edge index
    const int t  = gt & 3;             // row quarter: n = 4t..4t+3
    if (e >= E) return;

    int r, c;
    if (g_e64) {
        longlong2 ee = ((const longlong2*)edges_raw)[e];
        r = (int)ee.x; c = (int)ee.y;
    } else {
        int2 ee = ((const int2*)edges_raw)[e];
        r = ee.x; c = ee.y;
    }
    const float4* __restrict__ q4 = (const float4*)&g_P[r * DD];
    const float4* __restrict__ k4 = (const float4*)&g_P[c * DD];

    // ---- pass 1: s[n][m] = sum_h q[h][4t+n] * k[h][m] ----
    float s[4][16];
#pragma unroll
    for (int h = 0; h < NH; h++) {
        float4 qh = q4[h * 4 + t];                 // q[h][4t..4t+3]
        float4 k0 = k4[h * 4 + 0];
        float4 k1 = k4[h * 4 + 1];
        float4 k2 = k4[h * 4 + 2];
        float4 k3 = k4[h * 4 + 3];
        float km[16] = {k0.x, k0.y, k0.z, k0.w, k1.x, k1.y, k1.z, k1.w,
                        k2.x, k2.y, k2.z, k2.w, k3.x, k3.y, k3.z, k3.w};
        float qn[4] = {qh.x, qh.y, qh.z, qh.w};
#pragma unroll
        for (int n = 0; n < 4; n++) {
#pragma unroll
            for (int m = 0; m < 16; m++) {
                if (h == 0) s[n][m] = qn[n] * km[m];
                else        s[n][m] = fmaf(qn[n], km[m], s[n][m]);
            }
        }
    }

    // ---- softmax over m for each of the 4 rows (scale 1/sqrt(8) folded in) ----
    float inv[4];
#pragma unroll
    for (int n = 0; n < 4; n++) {
        float m0 = fmaxf(s[n][0],  s[n][1]);
        float m1 = fmaxf(s[n][2],  s[n][3]);
        float m2 = fmaxf(s[n][4],  s[n][5]);
        float m3 = fmaxf(s[n][6],  s[n][7]);
        float m4 = fmaxf(s[n][8],  s[n][9]);
        float m5 = fmaxf(s[n][10], s[n][11]);
        float m6 = fmaxf(s[n][12], s[n][13]);
        float m7 = fmaxf(s[n][14], s[n][15]);
        float mx = fmaxf(fmaxf(fmaxf(m0, m1), fmaxf(m2, m3)),
                         fmaxf(fmaxf(m4, m5), fmaxf(m6, m7)));
        float sum = 0.f;
#pragma unroll
        for (int m = 0; m < 16; m++) {
            float p = __expf((s[n][m] - mx) * 0.3535533906f);
            s[n][m] = p;
            sum += p;
        }
        inv[n] = 1.0f / sum;
    }

    // ---- pass 2: out[h][4t+n] = inv[n] * sum_m s[n][m]*k[h][m]; direct RED ----
    float* dstBase = &g_S[c * DD + t * 4];
#pragma unroll
    for (int h = 0; h < NH; h++) {
        float4 k0 = k4[h * 4 + 0];
        float4 k1 = k4[h * 4 + 1];
        float4 k2 = k4[h * 4 + 2];
        float4 k3 = k4[h * 4 + 3];
        float km[16] = {k0.x, k0.y, k0.z, k0.w, k1.x, k1.y, k1.z, k1.w,
                        k2.x, k2.y, k2.z, k2.w, k3.x, k3.y, k3.z, k3.w};
        float o[4];
#pragma unroll
        for (int n = 0; n < 4; n++) {
            float a0 = s[n][0] * km[0];
            float a1 = s[n][1] * km[1];
            float a2 = s[n][2] * km[2];
            float a3 = s[n][3] * km[3];
#pragma unroll
            for (int m = 4; m < 16; m += 4) {
                a0 = fmaf(s[n][m + 0], km[m + 0], a0);
                a1 = fmaf(s[n][m + 1], km[m + 1], a1);
                a2 = fmaf(s[n][m + 2], km[m + 2], a2);
                a3 = fmaf(s[n][m + 3], km[m + 3], a3);
            }
            o[n] = ((a0 + a1) + (a2 + a3)) * inv[n];
        }
        asm volatile("red.global.add.v4.f32 [%0], {%1,%2,%3,%4};"
                     :: "l"(dstBase + h * HDIM), "f"(o[0]), "f"(o[1]), "f"(o[2]), "f"(o[3])
                     : "memory");
    }
    if (t == 0) atomicAdd(&g_deg[c], 1.0f);
}

// ---------------- kernel C2: h = relu(x@W1a^T + S@Wc^T + deg*bc + b1) ----------------
__global__ __launch_bounds__(256) void k_mlp1(const float* __restrict__ x,
                                              const float* __restrict__ W1,
                                              const float* __restrict__ b1, int N) {
    __shared__ SmemGemm sm;
    float acc[4][8] = {};
    const int tid = threadIdx.x;
    const int rbase = blockIdx.x * 64;
    gemm64x128(x, W1, 2 * DD, rbase, N, tid, acc, &sm);   // x @ W1a^T (W1 row stride 256)
    gemm64x128(g_S, g_Wc, DD, rbase, N, tid, acc, &sm);   // S @ Wc^T
    const int tx = tid & 15, ty = tid >> 4;
#pragma unroll
    for (int i = 0; i < 4; i++) {
        int row = rbase + ty * 4 + i;
        if (row < N) {
            float dv = g_deg[row];
#pragma unroll
            for (int half = 0; half < 2; half++) {
                int c = half * 64 + tx * 4;
                float4 v;
                v.x = fmaxf(acc[i][half * 4 + 0] + b1[c + 0] + dv * g_bc[c + 0], 0.f);
                v.y = fmaxf(acc[i][half * 4 + 1] + b1[c + 1] + dv * g_bc[c + 1], 0.f);
                v.z = fmaxf(acc[i][half * 4 + 2] + b1[c + 2] + dv * g_bc[c + 2], 0.f);
                v.w = fmaxf(acc[i][half * 4 + 3] + b1[c + 3] + dv * g_bc[c + 3], 0.f);
                *(float4*)&g_Ht[row * DD + c] = v;
            }
        }
    }
}

// ---------------- kernel C3: y = h@W2^T + b2 ----------------
__global__ __launch_bounds__(256) void k_out(const float* __restrict__ W2,
                                             const float* __restrict__ b2,
                                             float* __restrict__ out, int N) {
    __shared__ SmemGemm sm;
    float acc[4][8] = {};
    const int tid = threadIdx.x;
    const int rbase = blockIdx.x * 64;
    gemm64x128(g_Ht, W2, DD, rbase, N, tid, acc, &sm);
    const int tx = tid & 15, ty = tid >> 4;
#pragma unroll
    for (int i = 0; i < 4; i++) {
        int row = rbase + ty * 4 + i;
        if (row < N) {
#pragma unroll
            for (int half = 0; half < 2; half++) {
                int c = half * 64 + tx * 4;
                float4 v;
                v.x = acc[i][half * 4 + 0] + b2[c + 0];
                v.y = acc[i][half * 4 + 1] + b2[c + 1];
                v.z = acc[i][half * 4 + 2] + b2[c + 2];
                v.w = acc[i][half * 4 + 3] + b2[c + 3];
                *(float4*)&out[row * DD + c] = v;
            }
        }
    }
}

// ---------------- launch ----------------
extern "C" void kernel_launch(void* const* d_in, const int* in_sizes, int n_in,
                              void* d_out, int out_size) {
    const float* x     = (const float*)d_in[0];
    const void*  edges = d_in[1];
    const float* Wp    = (const float*)d_in[2];
    const float* bp    = (const float*)d_in[3];
    const float* Wm    = (const float*)d_in[4];
    const float* bm    = (const float*)d_in[5];
    const float* W1    = (const float*)d_in[6];
    const float* b1    = (const float*)d_in[7];
    const float* W2    = (const float*)d_in[8];
    const float* b2    = (const float*)d_in[9];
    float* out = (float*)d_out;

    const int N = in_sizes[0] / DD;   // 20000
    const int E = in_sizes[1] / 2;    // 320000
    const int gN = (N + 63) / 64;

    k_detect<<<1, 32>>>((const long long*)edges, E * 2, N);
    k_fold<<<DD, DD>>>(W1, Wm, bm);
    k_proj<<<gN, 256>>>(x, Wp, bp, N);
    k_edge<<<(4 * E + 127) / 128, 128>>>(edges, E);
    k_mlp1<<<gN, 256>>>(x, W1, b1, N);
    k_out<<<gN, 256>>>(W2, b2, out, N);
}